// round 5
// baseline (speedup 1.0000x reference)
#include <cuda_runtime.h>
#include <math.h>

#define B_SZ 2048
#define M_SZ 1024
#define D_SZ 64
#define KDIM 128   // 2*D_SZ

typedef unsigned long long ull;

// ---------------- device scratch (no allocations allowed) ----------------
__device__ float  g_Bmat[KDIM * M_SZ];          // [k][m] : k<64 -> 1/Sigma, k>=64 -> -2*mut/Sigma
__device__ float2 g_hl[M_SZ];                   // (.x = -0.5*sum(mut^2/Sig + log Sig), .y = Lam)
__device__ float  g_P[M_SZ * KDIM];             // [m][k] : k<64 -> K, k>=64 -> c = v - K*mut
__device__ float  g_W[B_SZ * M_SZ];             // weights
__device__ float  g_Tpart[8 * B_SZ * KDIM];     // per-mchunk partial [T1|T2]
__device__ float  g_npart[8 * B_SZ];            // per-mchunk partial norm

// ---------------- f32x2 packed FMA helpers ----------------
__device__ __forceinline__ void ffma2(ull& d, ull a, ull b) {
    asm("fma.rn.f32x2 %0, %1, %2, %0;" : "+l"(d) : "l"(a), "l"(b));
}
__device__ __forceinline__ ull splat2(float x) {
    ull r;
    asm("mov.b64 %0, {%1, %1};" : "=l"(r) : "f"(x));
    return r;
}
__device__ __forceinline__ void unpack2(ull v, float& lo, float& hi) {
    asm("mov.b64 {%0, %1}, %2;" : "=f"(lo), "=f"(hi) : "l"(v));
}
union F4U { float4 f; ull u[2]; };

// ---------------- kernel 1: per-component parameter precompute ----------------
__global__ void precompute_params(const float* __restrict__ Mu0,
                                  const float* __restrict__ Mu1,
                                  const float* __restrict__ S0,
                                  const float* __restrict__ S1,
                                  const float* __restrict__ Lam,
                                  const float* __restrict__ tp,
                                  const float* __restrict__ ep) {
    int m = blockIdx.x;
    int d = threadIdx.x;      // 64 threads
    float t   = tp[0];
    float eps = ep[0];
    float eps2 = eps * eps;
    float eps4 = eps2 * eps2;
    float omt  = 1.0f - t;

    int id = m * D_SZ + d;
    float s0  = S0[id], s1 = S1[id];
    float mu0 = Mu0[id], mu1 = Mu1[id];

    float Ds = sqrtf(4.0f * s0 * s1 + eps4);
    float Cs = 0.5f * (Ds - eps2);
    float mt = omt * mu0 + t * mu1;
    float Sg = omt * omt * s0 + t * t * s1 + 2.0f * t * omt * (Cs + 0.5f * eps2);
    float Pt = t * s1 + omt * Cs;
    float Qt = omt * s0 + t * Cs;
    float St = Pt - Qt - eps2 * t;
    float inv = 1.0f / Sg;
    float Kk  = St * inv;
    float v   = mu1 - mu0;
    float c   = v - Kk * mt;

    g_Bmat[d * M_SZ + m]           = inv;
    g_Bmat[(D_SZ + d) * M_SZ + m]  = -2.0f * mt * inv;
    g_P[m * KDIM + d]              = Kk;
    g_P[m * KDIM + D_SZ + d]       = c;

    // reduce h = sum_d (mut^2*inv + log Sigma)
    __shared__ float red[64];
    red[d] = mt * mt * inv + logf(Sg);
    __syncthreads();
    #pragma unroll
    for (int s = 32; s > 0; s >>= 1) {
        if (d < s) red[d] += red[d + s];
        __syncthreads();
    }
    if (d == 0) g_hl[m] = make_float2(-0.5f * red[0], Lam[m]);
}

// ---------------- kernel 2: phase A GEMM + exp -> W ----------------
// grid (16 mblocks, 32 bblocks) = 512 CTAs, 128 threads.
// Tile 64 rows x 64 cols, K=128 in 8 steps of 16. Each thread: 4 rows x 8 cols.
__global__ __launch_bounds__(128, 8) void phaseA(const float* __restrict__ X) {
    __shared__ float As[16][68];    // [k][row] (padded)
    __shared__ float Bs[16][64];    // [k][col]

    int tx = threadIdx.x;
    int tr = tx >> 3;               // 0..15 -> row group of 4
    int tc = tx & 7;                // 0..7  -> col group of 8
    int brow0 = blockIdx.y * 64;
    int mcol0 = blockIdx.x * 64;

    ull acc2[2][8];
    #pragma unroll
    for (int i = 0; i < 2; i++)
        #pragma unroll
        for (int j = 0; j < 8; j++) acc2[i][j] = 0ULL;

    for (int k0 = 0; k0 < KDIM; k0 += 16) {
        // load A tile: 64 rows x 16 k, from X (square for k<64 half). 256 float4, 2/thread.
        #pragma unroll
        for (int i = 0; i < 2; i++) {
            int idx = tx + i * 128;          // 0..255
            int row = idx >> 2;              // 0..63
            int kq  = idx & 3;
            int k   = k0 + kq * 4;
            float4 v;
            if (k < D_SZ) {
                v = *(const float4*)&X[(brow0 + row) * D_SZ + k];
                v.x *= v.x; v.y *= v.y; v.z *= v.z; v.w *= v.w;
            } else {
                v = *(const float4*)&X[(brow0 + row) * D_SZ + k - D_SZ];
            }
            As[kq * 4 + 0][row] = v.x;
            As[kq * 4 + 1][row] = v.y;
            As[kq * 4 + 2][row] = v.z;
            As[kq * 4 + 3][row] = v.w;
        }
        // load B tile: 16 k x 64 m (256 float4, 2/thread)
        #pragma unroll
        for (int i = 0; i < 2; i++) {
            int idx = tx + i * 128;          // 0..255
            int kk = idx >> 4;
            int mq = idx & 15;
            *(float4*)&Bs[kk][mq * 4] =
                *(const float4*)&g_Bmat[(k0 + kk) * M_SZ + mcol0 + mq * 4];
        }
        __syncthreads();
        #pragma unroll
        for (int k = 0; k < 16; k++) {
            F4U a0, b0, b1;
            a0.f = *(const float4*)&As[k][tr * 4];
            b0.f = *(const float4*)&Bs[k][tc * 8];
            b1.f = *(const float4*)&Bs[k][tc * 8 + 4];
            ull bs[8];
            bs[0] = splat2(b0.f.x); bs[1] = splat2(b0.f.y);
            bs[2] = splat2(b0.f.z); bs[3] = splat2(b0.f.w);
            bs[4] = splat2(b1.f.x); bs[5] = splat2(b1.f.y);
            bs[6] = splat2(b1.f.z); bs[7] = splat2(b1.f.w);
            #pragma unroll
            for (int j = 0; j < 8; j++) {
                ffma2(acc2[0][j], a0.u[0], bs[j]);
                ffma2(acc2[1][j], a0.u[1], bs[j]);
            }
        }
        __syncthreads();
    }

    // unpack accumulators: 4 rows x 8 cols
    float acc[4][8];
    #pragma unroll
    for (int i = 0; i < 2; i++)
        #pragma unroll
        for (int j = 0; j < 8; j++)
            unpack2(acc2[i][j], acc[2 * i][j], acc[2 * i + 1][j]);

    // epilogue: logw = -0.5*S + hb ; clip ; W = exp(logw)*Lam
    float2 hl[8];
    #pragma unroll
    for (int j = 0; j < 8; j++) hl[j] = g_hl[mcol0 + tc * 8 + j];

    #pragma unroll
    for (int i = 0; i < 4; i++) {
        float w[8];
        #pragma unroll
        for (int j = 0; j < 8; j++) {
            float lw = fmaf(acc[i][j], -0.5f, hl[j].x);
            lw = fminf(fmaxf(lw, -50.0f), 50.0f);
            w[j] = __expf(lw) * hl[j].y;
        }
        float* dst = &g_W[(brow0 + tr * 4 + i) * M_SZ + mcol0 + tc * 8];
        *(float4*)&dst[0] = make_float4(w[0], w[1], w[2], w[3]);
        *(float4*)&dst[4] = make_float4(w[4], w[5], w[6], w[7]);
    }
}

// ---------------- kernel 3: phase B split-M GEMM -> partial T1,T2,norm ----------------
// grid (8 mchunks, 32 bblocks, 2 colhalves) = 512 CTAs, 128 threads.
// Tile: 64 rows x 64 cols (half 0 = K part, half 1 = c part), 128 m's in steps of 32.
__global__ __launch_bounds__(128, 8) void phaseB() {
    __shared__ float Ws[32][68];    // [m][row] (padded)
    __shared__ float Ps[32][64];    // [m][col]

    int tx = threadIdx.x;
    int tr = tx >> 3;               // 0..15 -> row group of 4
    int tc = tx & 7;                // 0..7  -> col group of 8
    int brow0 = blockIdx.y * 64;
    int chunk = blockIdx.x;
    int half  = blockIdx.z;         // 0 -> K cols [0,64), 1 -> c cols [64,128)
    int m0 = chunk * 128;

    ull acc2[2][8];
    #pragma unroll
    for (int i = 0; i < 2; i++)
        #pragma unroll
        for (int j = 0; j < 8; j++) acc2[i][j] = 0ULL;
    float nrm = 0.0f;

    for (int mt = 0; mt < 128; mt += 32) {
        // load W tile transposed: 64 rows x 32 m -> Ws[m][row]  (512 float4, 4/thread)
        #pragma unroll
        for (int i = 0; i < 4; i++) {
            int idx = tx + i * 128;          // 0..511
            int row = idx >> 3;              // 0..63
            int mq  = idx & 7;
            const float4 v = *(const float4*)&g_W[(brow0 + row) * M_SZ + m0 + mt + mq * 4];
            Ws[mq * 4 + 0][row] = v.x;
            Ws[mq * 4 + 1][row] = v.y;
            Ws[mq * 4 + 2][row] = v.z;
            Ws[mq * 4 + 3][row] = v.w;
        }
        // load P tile: 32 m x 64 cols (512 float4, 4/thread)
        #pragma unroll
        for (int i = 0; i < 4; i++) {
            int idx = tx + i * 128;          // 0..511
            int mm = idx >> 4;
            int cq = idx & 15;
            *(float4*)&Ps[mm][cq * 4] =
                *(const float4*)&g_P[(m0 + mt + mm) * KDIM + half * 64 + cq * 4];
        }
        __syncthreads();

        // norm partial: threads 0..63 each own one row (half 0 only)
        if (half == 0 && tx < 64) {
            #pragma unroll
            for (int mm = 0; mm < 32; mm++) nrm += Ws[mm][tx];
        }

        #pragma unroll
        for (int mm = 0; mm < 32; mm++) {
            F4U a0, b0, b1;
            a0.f = *(const float4*)&Ws[mm][tr * 4];
            b0.f = *(const float4*)&Ps[mm][tc * 8];
            b1.f = *(const float4*)&Ps[mm][tc * 8 + 4];
            ull bs[8];
            bs[0] = splat2(b0.f.x); bs[1] = splat2(b0.f.y);
            bs[2] = splat2(b0.f.z); bs[3] = splat2(b0.f.w);
            bs[4] = splat2(b1.f.x); bs[5] = splat2(b1.f.y);
            bs[6] = splat2(b1.f.z); bs[7] = splat2(b1.f.w);
            #pragma unroll
            for (int j = 0; j < 8; j++) {
                ffma2(acc2[0][j], a0.u[0], bs[j]);
                ffma2(acc2[1][j], a0.u[1], bs[j]);
            }
        }
        __syncthreads();
    }

    // unpack accumulators: 4 rows x 8 cols
    float acc[4][8];
    #pragma unroll
    for (int i = 0; i < 2; i++)
        #pragma unroll
        for (int j = 0; j < 8; j++)
            unpack2(acc2[i][j], acc[2 * i][j], acc[2 * i + 1][j]);

    // store partials
    #pragma unroll
    for (int i = 0; i < 4; i++) {
        int row = brow0 + tr * 4 + i;
        float* dst = &g_Tpart[(size_t)chunk * (B_SZ * KDIM) + row * KDIM + half * 64];
        *(float4*)&dst[tc * 8]     = make_float4(acc[i][0], acc[i][1], acc[i][2], acc[i][3]);
        *(float4*)&dst[tc * 8 + 4] = make_float4(acc[i][4], acc[i][5], acc[i][6], acc[i][7]);
    }
    if (half == 0 && tx < 64) g_npart[chunk * B_SZ + brow0 + tx] = nrm;
}

// ---------------- kernel 4: finalize (float4, high-MLP preload) ----------------
__global__ void finalize(const float* __restrict__ X, float* __restrict__ out) {
    int i = blockIdx.x * blockDim.x + threadIdx.x;   // 0..B*16-1 (float4 units)
    int b  = i >> 4;
    int d4 = (i & 15) * 4;

    float4 av[8], cv[8];
    float  nv[8];
    #pragma unroll
    for (int ch = 0; ch < 8; ch++) {
        const float* base = &g_Tpart[(size_t)ch * (B_SZ * KDIM) + b * KDIM];
        av[ch] = *(const float4*)&base[d4];
        cv[ch] = *(const float4*)&base[D_SZ + d4];
        nv[ch] = g_npart[ch * B_SZ + b];
    }

    float4 t1 = make_float4(0.f, 0.f, 0.f, 0.f);
    float4 t2 = make_float4(0.f, 0.f, 0.f, 0.f);
    float nr = 0.0f;
    #pragma unroll
    for (int ch = 0; ch < 8; ch++) {
        t1.x += av[ch].x; t1.y += av[ch].y; t1.z += av[ch].z; t1.w += av[ch].w;
        t2.x += cv[ch].x; t2.y += cv[ch].y; t2.z += cv[ch].z; t2.w += cv[ch].w;
        nr += nv[ch];
    }
    float inv = 1.0f / nr;
    float4 x = *(const float4*)&X[b * D_SZ + d4];
    float4 o;
    o.x = (x.x * t1.x + t2.x) * inv;
    o.y = (x.y * t1.y + t2.y) * inv;
    o.z = (x.z * t1.z + t2.z) * inv;
    o.w = (x.w * t1.w + t2.w) * inv;
    *(float4*)&out[b * D_SZ + d4] = o;
}

// ---------------- launch ----------------
extern "C" void kernel_launch(void* const* d_in, const int* in_sizes, int n_in,
                              void* d_out, int out_size) {
    const float* X   = (const float*)d_in[0];
    const float* Mu0 = (const float*)d_in[1];
    const float* Mu1 = (const float*)d_in[2];
    const float* S0  = (const float*)d_in[3];
    const float* S1  = (const float*)d_in[4];
    const float* Lam = (const float*)d_in[5];
    const float* tp  = (const float*)d_in[6];
    const float* ep  = (const float*)d_in[7];
    float* out = (float*)d_out;

    precompute_params<<<M_SZ, 64>>>(Mu0, Mu1, S0, S1, Lam, tp, ep);
    phaseA<<<dim3(M_SZ / 64, B_SZ / 64), 128>>>(X);
    phaseB<<<dim3(8, B_SZ / 64, 2), 128>>>();
    finalize<<<(B_SZ * 16) / 64, 64>>>(X, out);
}

// round 6
// speedup vs baseline: 1.4609x; 1.4609x over previous
#include <cuda_runtime.h>
#include <math.h>

#define B_SZ 2048
#define M_SZ 1024
#define D_SZ 64
#define KDIM 128   // 2*D_SZ

typedef unsigned long long ull;

// ---------------- device scratch (no allocations allowed) ----------------
__device__ float  g_Bmat[KDIM * M_SZ];          // [k][m] : k<64 -> 1/Sigma, k>=64 -> -2*mut/Sigma
__device__ float2 g_hl[M_SZ];                   // (.x = -0.5*sum(mut^2/Sig + log Sig), .y = Lam)
__device__ float  g_P[M_SZ * KDIM];             // [m][k] : k<64 -> K, k>=64 -> c = v - K*mut
__device__ float  g_W[B_SZ * M_SZ];             // weights
__device__ float  g_Tpart[8 * B_SZ * KDIM];     // per-mchunk partial [T1|T2]
__device__ float  g_npart[8 * B_SZ];            // per-mchunk partial norm

// ---------------- f32x2 packed FMA helpers ----------------
__device__ __forceinline__ void ffma2(ull& d, ull a, ull b) {
    asm("fma.rn.f32x2 %0, %1, %2, %0;" : "+l"(d) : "l"(a), "l"(b));
}
__device__ __forceinline__ ull splat2(float x) {
    ull r;
    asm("mov.b64 %0, {%1, %1};" : "=l"(r) : "f"(x));
    return r;
}
__device__ __forceinline__ void unpack2(ull v, float& lo, float& hi) {
    asm("mov.b64 {%0, %1}, %2;" : "=f"(lo), "=f"(hi) : "l"(v));
}
union F4U { float4 f; ull u[2]; };

// ---------------- kernel 1: per-component parameter precompute ----------------
__global__ void precompute_params(const float* __restrict__ Mu0,
                                  const float* __restrict__ Mu1,
                                  const float* __restrict__ S0,
                                  const float* __restrict__ S1,
                                  const float* __restrict__ Lam,
                                  const float* __restrict__ tp,
                                  const float* __restrict__ ep) {
    int m = blockIdx.x;
    int d = threadIdx.x;      // 64 threads
    float t   = tp[0];
    float eps = ep[0];
    float eps2 = eps * eps;
    float eps4 = eps2 * eps2;
    float omt  = 1.0f - t;

    int id = m * D_SZ + d;
    float s0  = S0[id], s1 = S1[id];
    float mu0 = Mu0[id], mu1 = Mu1[id];

    float Ds = sqrtf(4.0f * s0 * s1 + eps4);
    float Cs = 0.5f * (Ds - eps2);
    float mt = omt * mu0 + t * mu1;
    float Sg = omt * omt * s0 + t * t * s1 + 2.0f * t * omt * (Cs + 0.5f * eps2);
    float Pt = t * s1 + omt * Cs;
    float Qt = omt * s0 + t * Cs;
    float St = Pt - Qt - eps2 * t;
    float inv = 1.0f / Sg;
    float Kk  = St * inv;
    float v   = mu1 - mu0;
    float c   = v - Kk * mt;

    g_Bmat[d * M_SZ + m]           = inv;
    g_Bmat[(D_SZ + d) * M_SZ + m]  = -2.0f * mt * inv;
    g_P[m * KDIM + d]              = Kk;
    g_P[m * KDIM + D_SZ + d]       = c;

    // reduce h = sum_d (mut^2*inv + log Sigma)
    __shared__ float red[64];
    red[d] = mt * mt * inv + logf(Sg);
    __syncthreads();
    #pragma unroll
    for (int s = 32; s > 0; s >>= 1) {
        if (d < s) red[d] += red[d + s];
        __syncthreads();
    }
    if (d == 0) g_hl[m] = make_float2(-0.5f * red[0], Lam[m]);
}

// ---------------- kernel 2: phase A GEMM + exp -> W (double-buffered) ----------------
// grid (8 mblocks, 16 bblocks), 256 threads, 2 CTAs/SM. Tile 128x128, K in 8 steps of 16.
__global__ __launch_bounds__(256, 2) void phaseA(const float* __restrict__ X) {
    __shared__ float As[2][16][132];   // [buf][k][row] (padded)
    __shared__ float Bs[2][16][128];   // [buf][k][col]

    int tx = threadIdx.x;
    int tr = tx >> 4;               // 0..15 -> row group of 8
    int tc = tx & 15;               // 0..15 -> col group of 8
    int brow0 = blockIdx.y * 128;
    int mcol0 = blockIdx.x * 128;

    // fixed per-thread load indices
    int arow0 = tx >> 1;                  // thread handles rows arow0 (i=0) and +128? no:
    // A: 512 float4 per tile -> 2 per thread: idx = tx + i*256
    // B: 512 float4 per tile -> 2 per thread

    ull acc2[4][8];
    #pragma unroll
    for (int i = 0; i < 4; i++)
        #pragma unroll
        for (int j = 0; j < 8; j++) acc2[i][j] = 0ULL;

    float4 va[2], vb[2];

    // ---- prologue: load tile 0 ----
    #pragma unroll
    for (int i = 0; i < 2; i++) {
        int idx = tx + i * 256;
        int row = idx >> 2, kq = idx & 3;
        int k = kq * 4;
        float4 v;
        if (k < D_SZ) {
            v = *(const float4*)&X[(brow0 + row) * D_SZ + k];
            v.x *= v.x; v.y *= v.y; v.z *= v.z; v.w *= v.w;
        } else {
            v = *(const float4*)&X[(brow0 + row) * D_SZ + k - D_SZ];
        }
        va[i] = v;
        int kk = idx >> 5, mq = idx & 31;
        vb[i] = *(const float4*)&g_Bmat[kk * M_SZ + mcol0 + mq * 4];
    }
    #pragma unroll
    for (int i = 0; i < 2; i++) {
        int idx = tx + i * 256;
        int row = idx >> 2, kq = idx & 3;
        As[0][kq * 4 + 0][row] = va[i].x;
        As[0][kq * 4 + 1][row] = va[i].y;
        As[0][kq * 4 + 2][row] = va[i].z;
        As[0][kq * 4 + 3][row] = va[i].w;
        int kk = idx >> 5, mq = idx & 31;
        *(float4*)&Bs[0][kk][mq * 4] = vb[i];
    }
    __syncthreads();

    #pragma unroll
    for (int it = 0; it < 8; it++) {
        int cur = it & 1;
        // prefetch next tile's global loads (overlaps with compute below)
        if (it < 7) {
            int k0 = (it + 1) * 16;
            #pragma unroll
            for (int i = 0; i < 2; i++) {
                int idx = tx + i * 256;
                int row = idx >> 2, kq = idx & 3;
                int k = k0 + kq * 4;
                float4 v;
                if (k < D_SZ) {
                    v = *(const float4*)&X[(brow0 + row) * D_SZ + k];
                    v.x *= v.x; v.y *= v.y; v.z *= v.z; v.w *= v.w;
                } else {
                    v = *(const float4*)&X[(brow0 + row) * D_SZ + k - D_SZ];
                }
                va[i] = v;
                int kk = idx >> 5, mq = idx & 31;
                vb[i] = *(const float4*)&g_Bmat[(k0 + kk) * M_SZ + mcol0 + mq * 4];
            }
        }
        // compute on current buffer
        #pragma unroll
        for (int k = 0; k < 16; k++) {
            F4U a0, a1, b0, b1;
            a0.f = *(const float4*)&As[cur][k][tr * 8];
            a1.f = *(const float4*)&As[cur][k][tr * 8 + 4];
            b0.f = *(const float4*)&Bs[cur][k][tc * 8];
            b1.f = *(const float4*)&Bs[cur][k][tc * 8 + 4];
            ull ap[4] = { a0.u[0], a0.u[1], a1.u[0], a1.u[1] };
            ull bs[8];
            bs[0] = splat2(b0.f.x); bs[1] = splat2(b0.f.y);
            bs[2] = splat2(b0.f.z); bs[3] = splat2(b0.f.w);
            bs[4] = splat2(b1.f.x); bs[5] = splat2(b1.f.y);
            bs[6] = splat2(b1.f.z); bs[7] = splat2(b1.f.w);
            #pragma unroll
            for (int i = 0; i < 4; i++)
                #pragma unroll
                for (int j = 0; j < 8; j++)
                    ffma2(acc2[i][j], ap[i], bs[j]);
        }
        // store prefetched tile into the other buffer
        if (it < 7) {
            int nxt = cur ^ 1;
            #pragma unroll
            for (int i = 0; i < 2; i++) {
                int idx = tx + i * 256;
                int row = idx >> 2, kq = idx & 3;
                As[nxt][kq * 4 + 0][row] = va[i].x;
                As[nxt][kq * 4 + 1][row] = va[i].y;
                As[nxt][kq * 4 + 2][row] = va[i].z;
                As[nxt][kq * 4 + 3][row] = va[i].w;
                int kk = idx >> 5, mq = idx & 31;
                *(float4*)&Bs[nxt][kk][mq * 4] = vb[i];
            }
            __syncthreads();
        }
    }

    // unpack accumulators
    float acc[8][8];
    #pragma unroll
    for (int i = 0; i < 4; i++)
        #pragma unroll
        for (int j = 0; j < 8; j++)
            unpack2(acc2[i][j], acc[2 * i][j], acc[2 * i + 1][j]);

    // epilogue: logw = -0.5*S + hb ; clip ; W = exp(logw)*Lam
    float2 hl[8];
    #pragma unroll
    for (int j = 0; j < 8; j++) hl[j] = g_hl[mcol0 + tc * 8 + j];

    #pragma unroll
    for (int i = 0; i < 8; i++) {
        float w[8];
        #pragma unroll
        for (int j = 0; j < 8; j++) {
            float lw = fmaf(acc[i][j], -0.5f, hl[j].x);
            lw = fminf(fmaxf(lw, -50.0f), 50.0f);
            w[j] = __expf(lw) * hl[j].y;
        }
        float* dst = &g_W[(brow0 + tr * 8 + i) * M_SZ + mcol0 + tc * 8];
        *(float4*)&dst[0] = make_float4(w[0], w[1], w[2], w[3]);
        *(float4*)&dst[4] = make_float4(w[4], w[5], w[6], w[7]);
    }
}

// ---------------- kernel 3: phase B split-M GEMM (double-buffered) ----------------
// grid (8 mchunks, 16 bblocks), 256 threads, 2 CTAs/SM. 128 rows x 128 cols, 128 m in steps of 16.
__global__ __launch_bounds__(256, 2) void phaseB() {
    __shared__ float Ws[2][16][132];   // [buf][m][row] (padded)
    __shared__ float Ps[2][16][128];   // [buf][m][col]

    int tx = threadIdx.x;
    int tr = tx >> 4;               // row group of 8
    int tc = tx & 15;               // col group (4 T1 cols + 4 T2 cols)
    int brow0 = blockIdx.y * 128;
    int chunk = blockIdx.x;
    int m0 = chunk * 128;

    ull acc2[4][8];
    #pragma unroll
    for (int i = 0; i < 4; i++)
        #pragma unroll
        for (int j = 0; j < 8; j++) acc2[i][j] = 0ULL;
    float nrm = 0.0f;

    float4 vw[2], vp[2];

    // ---- prologue: load m-tile 0 ----
    #pragma unroll
    for (int i = 0; i < 2; i++) {
        int idx = tx + i * 256;
        int row = idx >> 2, mq = idx & 3;
        vw[i] = *(const float4*)&g_W[(brow0 + row) * M_SZ + m0 + mq * 4];
        int mm = idx >> 5, cq = idx & 31;
        vp[i] = *(const float4*)&g_P[(m0 + mm) * KDIM + cq * 4];
    }
    #pragma unroll
    for (int i = 0; i < 2; i++) {
        int idx = tx + i * 256;
        int row = idx >> 2, mq = idx & 3;
        Ws[0][mq * 4 + 0][row] = vw[i].x;
        Ws[0][mq * 4 + 1][row] = vw[i].y;
        Ws[0][mq * 4 + 2][row] = vw[i].z;
        Ws[0][mq * 4 + 3][row] = vw[i].w;
        int mm = idx >> 5, cq = idx & 31;
        *(float4*)&Ps[0][mm][cq * 4] = vp[i];
    }
    __syncthreads();

    #pragma unroll
    for (int it = 0; it < 8; it++) {
        int cur = it & 1;
        if (it < 7) {
            int mt = (it + 1) * 16;
            #pragma unroll
            for (int i = 0; i < 2; i++) {
                int idx = tx + i * 256;
                int row = idx >> 2, mq = idx & 3;
                vw[i] = *(const float4*)&g_W[(brow0 + row) * M_SZ + m0 + mt + mq * 4];
                int mm = idx >> 5, cq = idx & 31;
                vp[i] = *(const float4*)&g_P[(m0 + mt + mm) * KDIM + cq * 4];
            }
        }

        // norm partial: threads 0..127 each own one row
        if (tx < 128) {
            #pragma unroll
            for (int mm = 0; mm < 16; mm++) nrm += Ws[cur][mm][tx];
        }

        #pragma unroll
        for (int mm = 0; mm < 16; mm++) {
            F4U a0, a1, b0, b1;
            a0.f = *(const float4*)&Ws[cur][mm][tr * 8];
            a1.f = *(const float4*)&Ws[cur][mm][tr * 8 + 4];
            b0.f = *(const float4*)&Ps[cur][mm][tc * 4];          // K part
            b1.f = *(const float4*)&Ps[cur][mm][D_SZ + tc * 4];   // c part
            ull ap[4] = { a0.u[0], a0.u[1], a1.u[0], a1.u[1] };
            ull bs[8];
            bs[0] = splat2(b0.f.x); bs[1] = splat2(b0.f.y);
            bs[2] = splat2(b0.f.z); bs[3] = splat2(b0.f.w);
            bs[4] = splat2(b1.f.x); bs[5] = splat2(b1.f.y);
            bs[6] = splat2(b1.f.z); bs[7] = splat2(b1.f.w);
            #pragma unroll
            for (int i = 0; i < 4; i++)
                #pragma unroll
                for (int j = 0; j < 8; j++)
                    ffma2(acc2[i][j], ap[i], bs[j]);
        }

        if (it < 7) {
            int nxt = cur ^ 1;
            #pragma unroll
            for (int i = 0; i < 2; i++) {
                int idx = tx + i * 256;
                int row = idx >> 2, mq = idx & 3;
                Ws[nxt][mq * 4 + 0][row] = vw[i].x;
                Ws[nxt][mq * 4 + 1][row] = vw[i].y;
                Ws[nxt][mq * 4 + 2][row] = vw[i].z;
                Ws[nxt][mq * 4 + 3][row] = vw[i].w;
                int mm = idx >> 5, cq = idx & 31;
                *(float4*)&Ps[nxt][mm][cq * 4] = vp[i];
            }
            __syncthreads();
        }
    }

    // unpack accumulators
    float acc[8][8];
    #pragma unroll
    for (int i = 0; i < 4; i++)
        #pragma unroll
        for (int j = 0; j < 8; j++)
            unpack2(acc2[i][j], acc[2 * i][j], acc[2 * i + 1][j]);

    // store partials
    #pragma unroll
    for (int i = 0; i < 8; i++) {
        int row = brow0 + tr * 8 + i;
        float* dst = &g_Tpart[(size_t)chunk * (B_SZ * KDIM) + row * KDIM];
        *(float4*)&dst[tc * 4]        = make_float4(acc[i][0], acc[i][1], acc[i][2], acc[i][3]);
        *(float4*)&dst[D_SZ + tc * 4] = make_float4(acc[i][4], acc[i][5], acc[i][6], acc[i][7]);
    }
    if (tx < 128) g_npart[chunk * B_SZ + brow0 + tx] = nrm;
}

// ---------------- kernel 4: finalize (scalar, max threads) ----------------
__global__ void finalize(const float* __restrict__ X, float* __restrict__ out) {
    int i = blockIdx.x * blockDim.x + threadIdx.x;   // 0..B*64-1
    int b = i >> 6, d = i & 63;
    float t1 = 0.0f, t2 = 0.0f, nr = 0.0f;
    #pragma unroll
    for (int ch = 0; ch < 8; ch++) {
        t1 += g_Tpart[(size_t)ch * (B_SZ * KDIM) + b * KDIM + d];
        t2 += g_Tpart[(size_t)ch * (B_SZ * KDIM) + b * KDIM + D_SZ + d];
        nr += g_npart[ch * B_SZ + b];
    }
    out[i] = (X[i] * t1 + t2) / nr;
}

// ---------------- launch ----------------
extern "C" void kernel_launch(void* const* d_in, const int* in_sizes, int n_in,
                              void* d_out, int out_size) {
    const float* X   = (const float*)d_in[0];
    const float* Mu0 = (const float*)d_in[1];
    const float* Mu1 = (const float*)d_in[2];
    const float* S0  = (const float*)d_in[3];
    const float* S1  = (const float*)d_in[4];
    const float* Lam = (const float*)d_in[5];
    const float* tp  = (const float*)d_in[6];
    const float* ep  = (const float*)d_in[7];
    float* out = (float*)d_out;

    precompute_params<<<M_SZ, 64>>>(Mu0, Mu1, S0, S1, Lam, tp, ep);
    phaseA<<<dim3(M_SZ / 128, B_SZ / 128), 256>>>(X);
    phaseB<<<dim3(8, B_SZ / 128), 256>>>();
    finalize<<<(B_SZ * D_SZ) / 256, 256>>>(X, out);
}

// round 8
// speedup vs baseline: 1.7975x; 1.2304x over previous
#include <cuda_runtime.h>
#include <cuda_bf16.h>
#include <math.h>
#include <stdint.h>

#define B_SZ 2048
#define M_SZ 1024
#define D_SZ 64
#define KDIM 128   // 2*D_SZ

// ---------------- device scratch (no allocations allowed) ----------------
__device__ __nv_bfloat16 g_Xh[B_SZ * KDIM];     // [b][k] hi:  k<64 -> x^2, k>=64 -> x
__device__ __nv_bfloat16 g_Xl[B_SZ * KDIM];     // lo residual
__device__ __nv_bfloat16 g_Bmh[M_SZ * KDIM];    // [m][k] hi:  k<64 -> 1/Sig, k>=64 -> -2*mut/Sig
__device__ __nv_bfloat16 g_Bml[M_SZ * KDIM];
__device__ __nv_bfloat16 g_PTh[KDIM * M_SZ];    // [col][m] hi: col<64 -> K, col>=64 -> c
__device__ __nv_bfloat16 g_PTl[KDIM * M_SZ];
__device__ __nv_bfloat16 g_Wh[(size_t)B_SZ * M_SZ];
__device__ __nv_bfloat16 g_Wl[(size_t)B_SZ * M_SZ];
__device__ float2 g_hl[M_SZ];                   // (.x = -0.5*sum(mut^2/Sig + log Sig), .y = Lam)
__device__ float  g_Tpart[8 * B_SZ * KDIM];     // per-mchunk partial [T1|T2]
__device__ float  g_npart[8 * B_SZ];            // per-mblock partial norm

// ---------------- helpers ----------------
__device__ __forceinline__ uint32_t smem_u32(const void* p) {
    uint32_t a;
    asm("{ .reg .u64 t; cvta.to.shared.u64 t, %1; cvt.u32.u64 %0, t; }" : "=r"(a) : "l"(p));
    return a;
}
__device__ __forceinline__ void ldmx4(uint32_t* r, uint32_t addr) {
    asm volatile("ldmatrix.sync.aligned.m8n8.x4.shared.b16 {%0,%1,%2,%3}, [%4];"
        : "=r"(r[0]), "=r"(r[1]), "=r"(r[2]), "=r"(r[3]) : "r"(addr));
}
__device__ __forceinline__ void mma16816(float* c, const uint32_t* a, uint32_t b0, uint32_t b1) {
    asm volatile(
        "mma.sync.aligned.m16n8k16.row.col.f32.bf16.bf16.f32 "
        "{%0,%1,%2,%3}, {%4,%5,%6,%7}, {%8,%9}, {%0,%1,%2,%3};"
        : "+f"(c[0]), "+f"(c[1]), "+f"(c[2]), "+f"(c[3])
        : "r"(a[0]), "r"(a[1]), "r"(a[2]), "r"(a[3]), "r"(b0), "r"(b1));
}
__device__ __forceinline__ void split_bf(float v, __nv_bfloat16& h, __nv_bfloat16& l) {
    h = __float2bfloat16(v);
    l = __float2bfloat16(v - __bfloat162float(h));
}

// swizzled tile: 128 rows x 128 bf16 (16 chunks of 16B per row);
// byte offset = row*256 + ((chunk ^ (row & 7)) << 4). 256 threads.
__device__ __forceinline__ void load_tile(char* dst, const __nv_bfloat16* __restrict__ src,
                                          int stride, int tx) {
    #pragma unroll
    for (int i = 0; i < 8; i++) {
        int c   = tx + i * 256;          // 0..2047 chunk id
        int row = c >> 4;
        int ch  = c & 15;
        uint4 v = *(const uint4*)(src + (size_t)row * stride + ch * 8);
        uint32_t off = (uint32_t)(row * 256 + ((ch ^ (row & 7)) << 4));
        *(uint4*)(dst + off) = v;
    }
}

// ---------------- kernel 1: parameter precompute (split bf16 operands) ----------------
__global__ void precompute_params(const float* __restrict__ Mu0,
                                  const float* __restrict__ Mu1,
                                  const float* __restrict__ S0,
                                  const float* __restrict__ S1,
                                  const float* __restrict__ Lam,
                                  const float* __restrict__ tp,
                                  const float* __restrict__ ep) {
    int m = blockIdx.x;
    int d = threadIdx.x;      // 64 threads
    float t   = tp[0];
    float eps = ep[0];
    float eps2 = eps * eps;
    float eps4 = eps2 * eps2;
    float omt  = 1.0f - t;

    int id = m * D_SZ + d;
    float s0  = S0[id], s1 = S1[id];
    float mu0 = Mu0[id], mu1 = Mu1[id];

    float Ds = sqrtf(4.0f * s0 * s1 + eps4);
    float Cs = 0.5f * (Ds - eps2);
    float mt = omt * mu0 + t * mu1;
    float Sg = omt * omt * s0 + t * t * s1 + 2.0f * t * omt * (Cs + 0.5f * eps2);
    float Pt = t * s1 + omt * Cs;
    float Qt = omt * s0 + t * Cs;
    float St = Pt - Qt - eps2 * t;
    float inv = 1.0f / Sg;
    float Kk  = St * inv;
    float v   = mu1 - mu0;
    float c   = v - Kk * mt;

    __nv_bfloat16 h, l;
    split_bf(inv, h, l);              g_Bmh[m * KDIM + d] = h;          g_Bml[m * KDIM + d] = l;
    split_bf(-2.0f * mt * inv, h, l); g_Bmh[m * KDIM + D_SZ + d] = h;   g_Bml[m * KDIM + D_SZ + d] = l;
    split_bf(Kk, h, l);               g_PTh[d * M_SZ + m] = h;          g_PTl[d * M_SZ + m] = l;
    split_bf(c, h, l);                g_PTh[(D_SZ + d) * M_SZ + m] = h; g_PTl[(D_SZ + d) * M_SZ + m] = l;

    __shared__ float red[64];
    red[d] = mt * mt * inv + logf(Sg);
    __syncthreads();
    #pragma unroll
    for (int s = 32; s > 0; s >>= 1) {
        if (d < s) red[d] += red[d + s];
        __syncthreads();
    }
    if (d == 0) g_hl[m] = make_float2(-0.5f * red[0], Lam[m]);
}

// ---------------- kernel 2: split X into bf16 hi/lo Xcat ----------------
__global__ void splitX(const float* __restrict__ X) {
    int b = blockIdx.x;
    int d = threadIdx.x;   // 64
    float x = X[b * D_SZ + d];
    __nv_bfloat16 h, l;
    split_bf(x * x, h, l);
    g_Xh[b * KDIM + d] = h;  g_Xl[b * KDIM + d] = l;
    split_bf(x, h, l);
    g_Xh[b * KDIM + D_SZ + d] = h;  g_Xl[b * KDIM + D_SZ + d] = l;
}

// ================= shared warp-MMA core =================
// 256 threads = 8 warps, warp grid 2(m) x 4(n) over a 128x128 output tile.
// acc[mi][n8][4], mi: 4 x 16-row tiles (warp 64 rows), n8: 4 x 8-col tiles (warp 32 cols).
// Computes C = (Ah+Al)(Bh+Bl)^T with 4 cross products, K = 128.
struct Frag { float a[4][4][4]; };

__device__ __forceinline__ void gemm_core(float acc[4][4][4],
                                          uint32_t sAh, uint32_t sAl,
                                          uint32_t sBh, uint32_t sBl,
                                          int warp_m, int warp_n, int lane) {
    int s  = lane & 7;                  // swizzle xor (low 3 row bits)
    int q  = lane >> 3;                 // ldmatrix quadrant
    int hi = lane >> 4;                 // chunk low bit
    int rA = warp_m * 64 + (lane & 7) + ((q & 1) << 3);    // A row for this lane
    uint32_t rA256 = (uint32_t)(rA * 256);

    #pragma unroll
    for (int k = 0; k < 8; k++) {
        uint32_t cx = (uint32_t)((((2 * k + hi) ^ s)) << 4);

        uint32_t ah[4][4], al[4][4], bh[2][4], bl[2][4];
        #pragma unroll
        for (int mi = 0; mi < 4; mi++) {
            uint32_t off = rA256 + (uint32_t)(mi * 16 * 256) + cx;
            ldmx4(ah[mi], sAh + off);
            ldmx4(al[mi], sAl + off);
        }
        #pragma unroll
        for (int nt = 0; nt < 2; nt++) {
            int rB = warp_n * 32 + nt * 16 + (lane & 7) + ((q & 1) << 3);
            uint32_t off = (uint32_t)(rB * 256) + cx;
            ldmx4(bh[nt], sBh + off);
            ldmx4(bl[nt], sBl + off);
        }

        #pragma unroll
        for (int mi = 0; mi < 4; mi++)
            #pragma unroll
            for (int nt = 0; nt < 2; nt++)
                #pragma unroll
                for (int sb = 0; sb < 2; sb++) {
                    float* c = acc[mi][nt * 2 + sb];
                    mma16816(c, ah[mi], bh[nt][sb], bh[nt][sb + 2]);   // hh
                    mma16816(c, ah[mi], bl[nt][sb], bl[nt][sb + 2]);   // hl
                    mma16816(c, al[mi], bh[nt][sb], bh[nt][sb + 2]);   // lh
                    mma16816(c, al[mi], bl[nt][sb], bl[nt][sb + 2]);   // ll
                }
    }
}

// ---------------- phase A: S = Xcat @ Bm^T, epi: exp -> W hi/lo + norm partials ----------------
__global__ __launch_bounds__(256) void phaseA_mma() {
    extern __shared__ char smem[];
    __shared__ float2 s_hl[128];
    __shared__ float  s_nsum[128];

    int tx = threadIdx.x, wid = tx >> 5, lane = tx & 31;
    int warp_m = wid & 1, warp_n = wid >> 1;
    int g = lane >> 2, t = lane & 3;
    int mcol0 = blockIdx.x * 128;
    int brow0 = blockIdx.y * 128;

    char* bAh = smem;
    char* bAl = smem + 32768;
    char* bBh = smem + 65536;
    char* bBl = smem + 98304;

    if (tx < 128) { s_hl[tx] = g_hl[mcol0 + tx]; s_nsum[tx] = 0.0f; }

    load_tile(bAh, g_Xh  + (size_t)brow0 * KDIM, KDIM, tx);
    load_tile(bAl, g_Xl  + (size_t)brow0 * KDIM, KDIM, tx);
    load_tile(bBh, g_Bmh + (size_t)mcol0 * KDIM, KDIM, tx);
    load_tile(bBl, g_Bml + (size_t)mcol0 * KDIM, KDIM, tx);
    __syncthreads();

    float acc[4][4][4];
    #pragma unroll
    for (int i = 0; i < 4; i++)
        #pragma unroll
        for (int j = 0; j < 4; j++)
            #pragma unroll
            for (int e = 0; e < 4; e++) acc[i][j][e] = 0.0f;

    gemm_core(acc, smem_u32(bAh), smem_u32(bAl), smem_u32(bBh), smem_u32(bBl),
              warp_m, warp_n, lane);

    // epilogue
    #pragma unroll
    for (int mi = 0; mi < 4; mi++) {
        int r0 = warp_m * 64 + mi * 16 + g;     // local row
        int r1 = r0 + 8;
        float ns0 = 0.0f, ns1 = 0.0f;
        #pragma unroll
        for (int n8 = 0; n8 < 4; n8++) {
            int ml = warp_n * 32 + n8 * 8 + t * 2;
            float2 h0 = *(float2*)&s_hl[ml];        // pair (ml, ml+1) is two float2s
            float2 hlA = s_hl[ml], hlB = s_hl[ml + 1];
            (void)h0;
            float* c = acc[mi][n8];

            float lw0 = fmaf(c[0], -0.5f, hlA.x); lw0 = fminf(fmaxf(lw0, -50.f), 50.f);
            float lw1 = fmaf(c[1], -0.5f, hlB.x); lw1 = fminf(fmaxf(lw1, -50.f), 50.f);
            float lw2 = fmaf(c[2], -0.5f, hlA.x); lw2 = fminf(fmaxf(lw2, -50.f), 50.f);
            float lw3 = fmaf(c[3], -0.5f, hlB.x); lw3 = fminf(fmaxf(lw3, -50.f), 50.f);
            float w0 = __expf(lw0) * hlA.y;
            float w1 = __expf(lw1) * hlB.y;
            float w2 = __expf(lw2) * hlA.y;
            float w3 = __expf(lw3) * hlB.y;
            ns0 += w0 + w1;
            ns1 += w2 + w3;

            __nv_bfloat16 h, l;
            __nv_bfloat162 ph, pl;
            split_bf(w0, h, l); ph.x = h; pl.x = l;
            split_bf(w1, h, l); ph.y = h; pl.y = l;
            size_t o0 = (size_t)(brow0 + r0) * M_SZ + mcol0 + ml;
            *(__nv_bfloat162*)&g_Wh[o0] = ph;
            *(__nv_bfloat162*)&g_Wl[o0] = pl;
            split_bf(w2, h, l); ph.x = h; pl.x = l;
            split_bf(w3, h, l); ph.y = h; pl.y = l;
            size_t o1 = (size_t)(brow0 + r1) * M_SZ + mcol0 + ml;
            *(__nv_bfloat162*)&g_Wh[o1] = ph;
            *(__nv_bfloat162*)&g_Wl[o1] = pl;
        }
        // reduce over the quad (t = 0..3)
        ns0 += __shfl_xor_sync(0xFFFFFFFF, ns0, 1);
        ns0 += __shfl_xor_sync(0xFFFFFFFF, ns0, 2);
        ns1 += __shfl_xor_sync(0xFFFFFFFF, ns1, 1);
        ns1 += __shfl_xor_sync(0xFFFFFFFF, ns1, 2);
        if (t == 0) {
            atomicAdd(&s_nsum[r0], ns0);
            atomicAdd(&s_nsum[r1], ns1);
        }
    }
    __syncthreads();
    if (tx < 128) g_npart[blockIdx.x * B_SZ + brow0 + tx] = s_nsum[tx];
}

// ---------------- phase B: Tpart = W @ PT^T ----------------
__global__ __launch_bounds__(256) void phaseB_mma() {
    extern __shared__ char smem[];

    int tx = threadIdx.x, wid = tx >> 5, lane = tx & 31;
    int warp_m = wid & 1, warp_n = wid >> 1;
    int g = lane >> 2, t = lane & 3;
    int m0    = blockIdx.x * 128;
    int brow0 = blockIdx.y * 128;

    char* bAh = smem;
    char* bAl = smem + 32768;
    char* bBh = smem + 65536;
    char* bBl = smem + 98304;

    load_tile(bAh, g_Wh  + (size_t)brow0 * M_SZ + m0, M_SZ, tx);
    load_tile(bAl, g_Wl  + (size_t)brow0 * M_SZ + m0, M_SZ, tx);
    load_tile(bBh, g_PTh + m0, M_SZ, tx);
    load_tile(bBl, g_PTl + m0, M_SZ, tx);
    __syncthreads();

    float acc[4][4][4];
    #pragma unroll
    for (int i = 0; i < 4; i++)
        #pragma unroll
        for (int j = 0; j < 4; j++)
            #pragma unroll
            for (int e = 0; e < 4; e++) acc[i][j][e] = 0.0f;

    gemm_core(acc, smem_u32(bAh), smem_u32(bAl), smem_u32(bBh), smem_u32(bBl),
              warp_m, warp_n, lane);

    float* dst = &g_Tpart[(size_t)blockIdx.x * (B_SZ * KDIM)];
    #pragma unroll
    for (int mi = 0; mi < 4; mi++) {
        int r0 = brow0 + warp_m * 64 + mi * 16 + g;
        int r1 = r0 + 8;
        #pragma unroll
        for (int n8 = 0; n8 < 4; n8++) {
            int col = warp_n * 32 + n8 * 8 + t * 2;
            float* c = acc[mi][n8];
            *(float2*)&dst[(size_t)r0 * KDIM + col] = make_float2(c[0], c[1]);
            *(float2*)&dst[(size_t)r1 * KDIM + col] = make_float2(c[2], c[3]);
        }
    }
}

// ---------------- kernel 5: finalize ----------------
__global__ void finalize(const float* __restrict__ X, float* __restrict__ out) {
    int i = blockIdx.x * blockDim.x + threadIdx.x;   // 0..B*64-1
    int b = i >> 6, d = i & 63;
    float t1 = 0.0f, t2 = 0.0f, nr = 0.0f;
    #pragma unroll
    for (int ch = 0; ch < 8; ch++) {
        t1 += g_Tpart[(size_t)ch * (B_SZ * KDIM) + b * KDIM + d];
        t2 += g_Tpart[(size_t)ch * (B_SZ * KDIM) + b * KDIM + D_SZ + d];
        nr += g_npart[ch * B_SZ + b];
    }
    out[i] = (X[i] * t1 + t2) / nr;
}

// ---------------- launch ----------------
#define DYN_SMEM (4 * 32768)

extern "C" void kernel_launch(void* const* d_in, const int* in_sizes, int n_in,
                              void* d_out, int out_size) {
    const float* X   = (const float*)d_in[0];
    const float* Mu0 = (const float*)d_in[1];
    const float* Mu1 = (const float*)d_in[2];
    const float* S0  = (const float*)d_in[3];
    const float* S1  = (const float*)d_in[4];
    const float* Lam = (const float*)d_in[5];
    const float* tp  = (const float*)d_in[6];
    const float* ep  = (const float*)d_in[7];
    float* out = (float*)d_out;

    cudaFuncSetAttribute(phaseA_mma, cudaFuncAttributeMaxDynamicSharedMemorySize, DYN_SMEM);
    cudaFuncSetAttribute(phaseB_mma, cudaFuncAttributeMaxDynamicSharedMemorySize, DYN_SMEM);

    precompute_params<<<M_SZ, 64>>>(Mu0, Mu1, S0, S1, Lam, tp, ep);
    splitX<<<B_SZ, 64>>>(X);
    phaseA_mma<<<dim3(8, 16), 256, DYN_SMEM>>>();
    phaseB_mma<<<dim3(8, 16), 256, DYN_SMEM>>>();
    finalize<<<(B_SZ * D_SZ) / 256, 256>>>(X, out);
}

// round 9
// speedup vs baseline: 2.0737x; 1.1537x over previous
#include <cuda_runtime.h>
#include <cuda_bf16.h>
#include <math.h>
#include <stdint.h>

#define B_SZ 2048
#define M_SZ 1024
#define D_SZ 64
#define KDIM 128   // 2*D_SZ

// ---------------- device scratch (no allocations allowed) ----------------
__device__ __nv_bfloat16 g_Xh[B_SZ * KDIM];     // [b][k] hi:  k<64 -> x^2, k>=64 -> x
__device__ __nv_bfloat16 g_Xl[B_SZ * KDIM];     // lo residual
__device__ __nv_bfloat16 g_Bmh[M_SZ * KDIM];    // [m][k] hi:  k<64 -> 1/Sig, k>=64 -> -2*mut/Sig
__device__ __nv_bfloat16 g_Bml[M_SZ * KDIM];
__device__ __nv_bfloat16 g_PTh[KDIM * M_SZ];    // [col][m] hi: col<64 -> K, col>=64 -> c
__device__ __nv_bfloat16 g_PTl[KDIM * M_SZ];
__device__ __nv_bfloat16 g_Wh[(size_t)B_SZ * M_SZ];
__device__ __nv_bfloat16 g_Wl[(size_t)B_SZ * M_SZ];
__device__ float2 g_hl[M_SZ];                   // (.x = -0.5*sum(mut^2/Sig + log Sig), .y = Lam)
__device__ float  g_Tpart[(size_t)B_SZ * 8 * KDIM];  // [b][chunk][T1|T2]
__device__ float  g_npart[8 * B_SZ];            // per-mblock partial norm

// ---------------- helpers ----------------
__device__ __forceinline__ uint32_t smem_u32(const void* p) {
    uint32_t a;
    asm("{ .reg .u64 t; cvta.to.shared.u64 t, %1; cvt.u32.u64 %0, t; }" : "=r"(a) : "l"(p));
    return a;
}
__device__ __forceinline__ void ldmx4(uint32_t* r, uint32_t addr) {
    asm volatile("ldmatrix.sync.aligned.m8n8.x4.shared.b16 {%0,%1,%2,%3}, [%4];"
        : "=r"(r[0]), "=r"(r[1]), "=r"(r[2]), "=r"(r[3]) : "r"(addr));
}
__device__ __forceinline__ void mma16816(float* c, const uint32_t* a, uint32_t b0, uint32_t b1) {
    asm volatile(
        "mma.sync.aligned.m16n8k16.row.col.f32.bf16.bf16.f32 "
        "{%0,%1,%2,%3}, {%4,%5,%6,%7}, {%8,%9}, {%0,%1,%2,%3};"
        : "+f"(c[0]), "+f"(c[1]), "+f"(c[2]), "+f"(c[3])
        : "r"(a[0]), "r"(a[1]), "r"(a[2]), "r"(a[3]), "r"(b0), "r"(b1));
}
__device__ __forceinline__ void cp16(uint32_t dst, const void* src) {
    asm volatile("cp.async.cg.shared.global [%0], [%1], 16;" :: "r"(dst), "l"(src));
}
#define CP_WAIT_ALL() asm volatile("cp.async.commit_group;\n\tcp.async.wait_group 0;" ::: "memory")

__device__ __forceinline__ void split_bf(float v, __nv_bfloat16& h, __nv_bfloat16& l) {
    h = __float2bfloat16(v);
    l = __float2bfloat16(v - __bfloat162float(h));
}

// swizzled tile: 128 rows x 128 bf16; byte offset = row*256 + ((chunk ^ (row&7)) << 4).
// cp.async version, 512 threads.
__device__ __forceinline__ void load_tile_async(uint32_t dst, const __nv_bfloat16* __restrict__ src,
                                                int stride, int tx) {
    #pragma unroll
    for (int i = 0; i < 4; i++) {
        int c   = tx + i * 512;          // 0..2047 chunk id
        int row = c >> 4;
        int ch  = c & 15;
        uint32_t off = (uint32_t)(row * 256 + ((ch ^ (row & 7)) << 4));
        cp16(dst + off, src + (size_t)row * stride + ch * 8);
    }
}

// ---------------- kernel 1: parameter precompute (split bf16 operands) ----------------
__global__ void precompute_params(const float* __restrict__ Mu0,
                                  const float* __restrict__ Mu1,
                                  const float* __restrict__ S0,
                                  const float* __restrict__ S1,
                                  const float* __restrict__ Lam,
                                  const float* __restrict__ tp,
                                  const float* __restrict__ ep) {
    int m = blockIdx.x;
    int d = threadIdx.x;      // 64 threads
    float t   = tp[0];
    float eps = ep[0];
    float eps2 = eps * eps;
    float eps4 = eps2 * eps2;
    float omt  = 1.0f - t;

    int id = m * D_SZ + d;
    float s0  = S0[id], s1 = S1[id];
    float mu0 = Mu0[id], mu1 = Mu1[id];

    float Ds = sqrtf(4.0f * s0 * s1 + eps4);
    float Cs = 0.5f * (Ds - eps2);
    float mt = omt * mu0 + t * mu1;
    float Sg = omt * omt * s0 + t * t * s1 + 2.0f * t * omt * (Cs + 0.5f * eps2);
    float Pt = t * s1 + omt * Cs;
    float Qt = omt * s0 + t * Cs;
    float St = Pt - Qt - eps2 * t;
    float inv = 1.0f / Sg;
    float Kk  = St * inv;
    float v   = mu1 - mu0;
    float c   = v - Kk * mt;

    __nv_bfloat16 h, l;
    split_bf(inv, h, l);              g_Bmh[m * KDIM + d] = h;          g_Bml[m * KDIM + d] = l;
    split_bf(-2.0f * mt * inv, h, l); g_Bmh[m * KDIM + D_SZ + d] = h;   g_Bml[m * KDIM + D_SZ + d] = l;
    split_bf(Kk, h, l);               g_PTh[d * M_SZ + m] = h;          g_PTl[d * M_SZ + m] = l;
    split_bf(c, h, l);                g_PTh[(D_SZ + d) * M_SZ + m] = h; g_PTl[(D_SZ + d) * M_SZ + m] = l;

    __shared__ float red[64];
    red[d] = mt * mt * inv + logf(Sg);
    __syncthreads();
    #pragma unroll
    for (int s = 32; s > 0; s >>= 1) {
        if (d < s) red[d] += red[d + s];
        __syncthreads();
    }
    if (d == 0) g_hl[m] = make_float2(-0.5f * red[0], Lam[m]);
}

// ---------------- kernel 2: split X into bf16 hi/lo Xcat ----------------
__global__ void splitX(const float* __restrict__ X) {
    int b = blockIdx.x;
    int d = threadIdx.x;   // 64
    float x = X[b * D_SZ + d];
    __nv_bfloat16 h, l;
    split_bf(x * x, h, l);
    g_Xh[b * KDIM + d] = h;  g_Xl[b * KDIM + d] = l;
    split_bf(x, h, l);
    g_Xh[b * KDIM + D_SZ + d] = h;  g_Xl[b * KDIM + D_SZ + d] = l;
}

// ================= shared warp-MMA core =================
// 512 threads = 16 warps, warp grid 4(m) x 4(n); warp tile 32 rows x 32 cols.
// acc[mi][n8][4]: mi 2 x 16-row, n8 4 x 8-col.
// Computes C ~= (Ah+Al)(Bh+Bl)^T with hh+hl+lh (ll dropped, ~2^-16), K = 128.
__device__ __forceinline__ void gemm_core(float acc[2][4][4],
                                          uint32_t sAh, uint32_t sAl,
                                          uint32_t sBh, uint32_t sBl,
                                          int warp_m, int warp_n, int lane) {
    int s  = lane & 7;
    int q8 = (lane >> 3) & 1;
    int hi = lane >> 4;

    #pragma unroll
    for (int k = 0; k < 8; k++) {
        uint32_t cx = (uint32_t)(((2 * k + hi) ^ s) << 4);

        uint32_t ah[2][4], al[2][4], bh[2][4], bl[2][4];
        #pragma unroll
        for (int mi = 0; mi < 2; mi++) {
            int rA = warp_m * 32 + mi * 16 + s + (q8 << 3);
            uint32_t off = (uint32_t)(rA * 256) + cx;
            ldmx4(ah[mi], sAh + off);
            ldmx4(al[mi], sAl + off);
        }
        #pragma unroll
        for (int nt = 0; nt < 2; nt++) {
            int rB = warp_n * 32 + nt * 16 + s + (q8 << 3);
            uint32_t off = (uint32_t)(rB * 256) + cx;
            ldmx4(bh[nt], sBh + off);
            ldmx4(bl[nt], sBl + off);
        }

        #pragma unroll
        for (int mi = 0; mi < 2; mi++)
            #pragma unroll
            for (int nt = 0; nt < 2; nt++)
                #pragma unroll
                for (int sb = 0; sb < 2; sb++) {
                    float* c = acc[mi][nt * 2 + sb];
                    mma16816(c, ah[mi], bh[nt][sb], bh[nt][sb + 2]);   // hh
                    mma16816(c, ah[mi], bl[nt][sb], bl[nt][sb + 2]);   // hl
                    mma16816(c, al[mi], bh[nt][sb], bh[nt][sb + 2]);   // lh
                }
    }
}

// ---------------- phase A: S = Xcat @ Bm^T, epi: exp -> W hi/lo + norm partials ----------------
__global__ __launch_bounds__(512) void phaseA_mma() {
    extern __shared__ char smem[];
    __shared__ float2 s_hl[128];
    __shared__ float  s_nsum[128];

    int tx = threadIdx.x, wid = tx >> 5, lane = tx & 31;
    int warp_m = wid & 3, warp_n = wid >> 2;
    int g = lane >> 2, t = lane & 3;
    int mcol0 = blockIdx.x * 128;
    int brow0 = blockIdx.y * 128;

    uint32_t sAh = smem_u32(smem);
    uint32_t sAl = sAh + 32768;
    uint32_t sBh = sAh + 65536;
    uint32_t sBl = sAh + 98304;

    if (tx < 128) { s_hl[tx] = g_hl[mcol0 + tx]; s_nsum[tx] = 0.0f; }

    load_tile_async(sAh, g_Xh  + (size_t)brow0 * KDIM, KDIM, tx);
    load_tile_async(sAl, g_Xl  + (size_t)brow0 * KDIM, KDIM, tx);
    load_tile_async(sBh, g_Bmh + (size_t)mcol0 * KDIM, KDIM, tx);
    load_tile_async(sBl, g_Bml + (size_t)mcol0 * KDIM, KDIM, tx);
    CP_WAIT_ALL();
    __syncthreads();

    float acc[2][4][4];
    #pragma unroll
    for (int i = 0; i < 2; i++)
        #pragma unroll
        for (int j = 0; j < 4; j++)
            #pragma unroll
            for (int e = 0; e < 4; e++) acc[i][j][e] = 0.0f;

    gemm_core(acc, sAh, sAl, sBh, sBl, warp_m, warp_n, lane);

    // epilogue
    #pragma unroll
    for (int mi = 0; mi < 2; mi++) {
        int r0 = warp_m * 32 + mi * 16 + g;     // local row
        int r1 = r0 + 8;
        float ns0 = 0.0f, ns1 = 0.0f;
        #pragma unroll
        for (int n8 = 0; n8 < 4; n8++) {
            int ml = warp_n * 32 + n8 * 8 + t * 2;
            float2 hlA = s_hl[ml], hlB = s_hl[ml + 1];
            float* c = acc[mi][n8];

            float lw0 = fmaf(c[0], -0.5f, hlA.x); lw0 = fminf(fmaxf(lw0, -50.f), 50.f);
            float lw1 = fmaf(c[1], -0.5f, hlB.x); lw1 = fminf(fmaxf(lw1, -50.f), 50.f);
            float lw2 = fmaf(c[2], -0.5f, hlA.x); lw2 = fminf(fmaxf(lw2, -50.f), 50.f);
            float lw3 = fmaf(c[3], -0.5f, hlB.x); lw3 = fminf(fmaxf(lw3, -50.f), 50.f);
            float w0 = __expf(lw0) * hlA.y;
            float w1 = __expf(lw1) * hlB.y;
            float w2 = __expf(lw2) * hlA.y;
            float w3 = __expf(lw3) * hlB.y;
            ns0 += w0 + w1;
            ns1 += w2 + w3;

            __nv_bfloat16 h, l;
            __nv_bfloat162 ph, pl;
            split_bf(w0, h, l); ph.x = h; pl.x = l;
            split_bf(w1, h, l); ph.y = h; pl.y = l;
            size_t o0 = (size_t)(brow0 + r0) * M_SZ + mcol0 + ml;
            *(__nv_bfloat162*)&g_Wh[o0] = ph;
            *(__nv_bfloat162*)&g_Wl[o0] = pl;
            split_bf(w2, h, l); ph.x = h; pl.x = l;
            split_bf(w3, h, l); ph.y = h; pl.y = l;
            size_t o1 = (size_t)(brow0 + r1) * M_SZ + mcol0 + ml;
            *(__nv_bfloat162*)&g_Wh[o1] = ph;
            *(__nv_bfloat162*)&g_Wl[o1] = pl;
        }
        ns0 += __shfl_xor_sync(0xFFFFFFFF, ns0, 1);
        ns0 += __shfl_xor_sync(0xFFFFFFFF, ns0, 2);
        ns1 += __shfl_xor_sync(0xFFFFFFFF, ns1, 1);
        ns1 += __shfl_xor_sync(0xFFFFFFFF, ns1, 2);
        if (t == 0) {
            atomicAdd(&s_nsum[r0], ns0);
            atomicAdd(&s_nsum[r1], ns1);
        }
    }
    __syncthreads();
    if (tx < 128) g_npart[blockIdx.x * B_SZ + brow0 + tx] = s_nsum[tx];
}

// ---------------- phase B: Tpart[b][chunk][:] = W @ PT^T ----------------
__global__ __launch_bounds__(512) void phaseB_mma() {
    extern __shared__ char smem[];

    int tx = threadIdx.x, wid = tx >> 5, lane = tx & 31;
    int warp_m = wid & 3, warp_n = wid >> 2;
    int g = lane >> 2, t = lane & 3;
    int m0    = blockIdx.x * 128;
    int chunk = blockIdx.x;
    int brow0 = blockIdx.y * 128;

    uint32_t sAh = smem_u32(smem);
    uint32_t sAl = sAh + 32768;
    uint32_t sBh = sAh + 65536;
    uint32_t sBl = sAh + 98304;

    load_tile_async(sAh, g_Wh  + (size_t)brow0 * M_SZ + m0, M_SZ, tx);
    load_tile_async(sAl, g_Wl  + (size_t)brow0 * M_SZ + m0, M_SZ, tx);
    load_tile_async(sBh, g_PTh + m0, M_SZ, tx);
    load_tile_async(sBl, g_PTl + m0, M_SZ, tx);
    CP_WAIT_ALL();
    __syncthreads();

    float acc[2][4][4];
    #pragma unroll
    for (int i = 0; i < 2; i++)
        #pragma unroll
        for (int j = 0; j < 4; j++)
            #pragma unroll
            for (int e = 0; e < 4; e++) acc[i][j][e] = 0.0f;

    gemm_core(acc, sAh, sAl, sBh, sBl, warp_m, warp_n, lane);

    #pragma unroll
    for (int mi = 0; mi < 2; mi++) {
        int r0 = brow0 + warp_m * 32 + mi * 16 + g;
        int r1 = r0 + 8;
        #pragma unroll
        for (int n8 = 0; n8 < 4; n8++) {
            int col = warp_n * 32 + n8 * 8 + t * 2;
            float* c = acc[mi][n8];
            *(float2*)&g_Tpart[((size_t)r0 * 8 + chunk) * KDIM + col] = make_float2(c[0], c[1]);
            *(float2*)&g_Tpart[((size_t)r1 * 8 + chunk) * KDIM + col] = make_float2(c[2], c[3]);
        }
    }
}

// ---------------- kernel 5: finalize ----------------
__global__ void finalize(const float* __restrict__ X, float* __restrict__ out) {
    int i = blockIdx.x * blockDim.x + threadIdx.x;   // 0..B*64-1
    int b = i >> 6, d = i & 63;
    float t1 = 0.0f, t2 = 0.0f, nr = 0.0f;
    #pragma unroll
    for (int ch = 0; ch < 8; ch++) {
        t1 += g_Tpart[((size_t)b * 8 + ch) * KDIM + d];
        t2 += g_Tpart[((size_t)b * 8 + ch) * KDIM + D_SZ + d];
        nr += g_npart[ch * B_SZ + b];
    }
    out[i] = (X[i] * t1 + t2) / nr;
}

// ---------------- launch ----------------
#define DYN_SMEM (4 * 32768)

extern "C" void kernel_launch(void* const* d_in, const int* in_sizes, int n_in,
                              void* d_out, int out_size) {
    const float* X   = (const float*)d_in[0];
    const float* Mu0 = (const float*)d_in[1];
    const float* Mu1 = (const float*)d_in[2];
    const float* S0  = (const float*)d_in[3];
    const float* S1  = (const float*)d_in[4];
    const float* Lam = (const float*)d_in[5];
    const float* tp  = (const float*)d_in[6];
    const float* ep  = (const float*)d_in[7];
    float* out = (float*)d_out;

    cudaFuncSetAttribute(phaseA_mma, cudaFuncAttributeMaxDynamicSharedMemorySize, DYN_SMEM);
    cudaFuncSetAttribute(phaseB_mma, cudaFuncAttributeMaxDynamicSharedMemorySize, DYN_SMEM);

    precompute_params<<<M_SZ, 64>>>(Mu0, Mu1, S0, S1, Lam, tp, ep);
    splitX<<<B_SZ, 64>>>(X);
    phaseA_mma<<<dim3(8, 16), 512, DYN_SMEM>>>();
    phaseB_mma<<<dim3(8, 16), 512, DYN_SMEM>>>();
    finalize<<<(B_SZ * D_SZ) / 256, 256>>>(X, out);
}